// round 16
// baseline (speedup 1.0000x reference)
#include <cuda_runtime.h>

typedef unsigned long long u64;

// ---- packed f32x2 helpers (Blackwell sm_103a) ----
__device__ __forceinline__ u64 pk2(float a, float b) {
    u64 r; asm("mov.b64 %0,{%1,%2};" : "=l"(r) : "f"(a), "f"(b)); return r;
}
__device__ __forceinline__ void fma2(u64 &d, u64 a, u64 b) {
    asm("fma.rn.f32x2 %0,%1,%2,%0;" : "+l"(d) : "l"(a), "l"(b));
}
__device__ __forceinline__ u64 mul2(u64 a, u64 b) {
    u64 r; asm("mul.rn.f32x2 %0,%1,%2;" : "=l"(r) : "l"(a), "l"(b)); return r;
}
__device__ __forceinline__ u64 add2(u64 a, u64 b) {
    u64 r; asm("add.rn.f32x2 %0,%1,%2;" : "=l"(r) : "l"(a), "l"(b)); return r;
}
__device__ __forceinline__ void up2(u64 v, float &x, float &y) {
    asm("mov.b64 {%0,%1},%2;" : "=f"(x), "=f"(y) : "l"(v));
}
__device__ __forceinline__ void cp8(unsigned sa, const float2* ga) {
    asm volatile("cp.async.ca.shared.global [%0],[%1],8;" :: "r"(sa), "l"(ga));
}
__device__ __forceinline__ void cp_commit() {
    asm volatile("cp.async.commit_group;");
}
__device__ __forceinline__ void cp_wait1() {
    asm volatile("cp.async.wait_group 1;");
}

// Shapes: x:(64,4,2,256,256) w:(4,4,128,128,16,2) bias:(4,128,128,2) out:(64,4,2,128,128)
#define NPC 64                // all n per block (weights read from DRAM once)
#define XBUF 128              // float2 per x slice: 4(ir) * 4c * 8y = 1 KB
#define NBUF 16               // ring depth (slices), 16 KB
#define NSTR 262144           // per-n stride in x, float2 units

// Block = 128 threads = 4 warps, 6 blocks/SM (6 independent barrier domains).
//   warp w owns output channel p = w; lane = c*8 + dy; y = y0 + dy (y-tile of 8).
// Grid = 128 (x) * 16 (y-tile) = 2048.
// Weight prologue: ONE pass (16 KB smem, MLP-8 LDGs, single sync) instead of
// four serialized rounds. x ring via cp.async 16-buffer ring;
// FOUR n-slices per barrier window; refill issued before wait+sync.
__global__ void __launch_bounds__(128, 6) ttn_kernel(
    const float* __restrict__ X, const float* __restrict__ W,
    const float* __restrict__ B, float* __restrict__ O)
{
    __shared__ __align__(16) float4 smw[1024];           // 16 KB weight staging
    __shared__ __align__(16) float2 xsm[NBUF * XBUF];    // 16 KB x ring

    const int tid  = threadIdx.x;
    const int warp = tid >> 5;     // = p
    const int lane = tid & 31;
    const int c    = lane >> 3;
    const int dy   = lane & 7;

    const int bid = blockIdx.x;
    const int xp  = bid >> 4;
    const int y0  = (bid & 15) * 8;

    // ---- x staging: identity map, 1 float2 per thread per slice ----
    const int ir_ = tid >> 5, c_ = (tid >> 3) & 3, yy_ = tid & 7;
    const int i_ = ir_ >> 1, r_ = ir_ & 1;
    const int goff = (c_ * 2 + i_) * 32768 + (2 * xp + r_) * 128 + y0 + yy_;

    unsigned sbase = (unsigned)__cvta_generic_to_shared(xsm);
    unsigned sa    = sbase + (unsigned)tid * 8u;

    // prologue: windows 0 and 1 (slices 0..7) as two 4-slice groups
    {
        const float2* gp = (const float2*)X + goff;
#pragma unroll
        for (int s = 0; s < 4; ++s)
            cp8(sa + (unsigned)s * XBUF * 8u, gp + (long)s * NSTR);
        cp_commit();
#pragma unroll
        for (int s = 4; s < 8; ++s)
            cp8(sa + (unsigned)s * XBUF * 8u, gp + (long)s * NSTR);
        cp_commit();
    }

    // ---- single-pass weight staging: 8 MLP LDG.128 -> STS -> 1 sync -> LDS ----
    // layout: [r(4)][p(4)][yy(8)][j(8)] float4, swizzled j^yy^(p<<1)
    u64 w2[16];
    {
#pragma unroll
        for (int k = 0; k < 8; ++k) {
            int G  = k * 128 + tid;        // 0..1023
            int r  = G >> 8;
            int p  = (G >> 6) & 3;
            int yy = (G >> 3) & 7;
            int j  = G & 7;
            float4 v = __ldg((const float4*)W +
                             (((r * 4 + p) * 16384 + xp * 128 + y0 + yy) * 8 + j));
            smw[r * 256 + p * 64 + yy * 8 + (j ^ yy ^ (p << 1))] = v;
        }
        __syncthreads();
#pragma unroll
        for (int t = 0; t < 8; ++t) {
            float4 v = smw[c * 256 + warp * 64 + dy * 8 + (t ^ dy ^ (warp << 1))];
            w2[2 * t]     = pk2(v.x, v.y);
            w2[2 * t + 1] = pk2(v.z, v.w);
        }
    }

    const float2 bz = *(const float2*)(B + ((warp * 128 + xp) * 128 + y0 + dy) * 2);
    const int OSTR = 4 * 2 * 16384;
    int oo = (warp * 2) * 16384 + xp * 128 + y0 + dy;   // advances per slice

    // moving refill pointer: window w refills slices 4w+8..4w+11
    const float2* gref = (const float2*)X + goff + 8L * NSTR;

#pragma unroll 4
    for (int w = 0; w < NPC / 4; ++w) {
        const int s0 = 4 * w;

        // refill BEFORE wait/sync (targets disjoint from windows w-1..w+1)
        if (w < NPC / 4 - 2) {
#pragma unroll
            for (int j = 0; j < 4; ++j)
                cp8(sa + (unsigned)((s0 + 8 + j) & 15) * XBUF * 8u,
                    gref + (long)j * NSTR);
        }
        cp_commit();
        gref += 4L * NSTR;

        cp_wait1();          // group holding this window's slices has landed
        __syncthreads();     // visible; retires window w-1's reads

        // two sub-pairs of slices; register-light
#pragma unroll
        for (int h = 0; h < 2; ++h) {
            const float2* bufA = xsm + ((s0 + 2 * h)     & 15) * XBUF;
            const float2* bufB = xsm + ((s0 + 2 * h + 1) & 15) * XBUF;
            float2 A0 = bufA[lane],      A1 = bufA[32 + lane];
            float2 A2 = bufA[64 + lane], A3 = bufA[96 + lane];
            float2 B0 = bufB[lane],      B1 = bufB[32 + lane];
            float2 B2 = bufB[64 + lane], B3 = bufB[96 + lane];

            u64 accA, accB;
            {
                const float a0 = A0.x, e0 = A0.y, b0 = A1.x, f0 = A1.y;
                const float a1 = A2.x, e1 = A2.y, b1 = A3.x, f1 = A3.y;
                u64 ab2[4] = { pk2(a0*b0,a0*b0), pk2(a0*b1,a0*b1),
                               pk2(a1*b0,a1*b0), pk2(a1*b1,a1*b1) };
                u64 ef2[4] = { pk2(e0*f0,e0*f0), pk2(e0*f1,e0*f1),
                               pk2(e1*f0,e1*f0), pk2(e1*f1,e1*f1) };
#pragma unroll
                for (int g = 0; g < 4; ++g) {
                    u64 t0 = mul2(w2[g*4+0], ef2[0]);
                    fma2(t0, w2[g*4+1], ef2[1]);
                    fma2(t0, w2[g*4+2], ef2[2]);
                    fma2(t0, w2[g*4+3], ef2[3]);
                    if (g == 0) accA = mul2(ab2[0], t0);
                    else        fma2(accA, ab2[g], t0);
                }
            }
            {
                const float a0 = B0.x, e0 = B0.y, b0 = B1.x, f0 = B1.y;
                const float a1 = B2.x, e1 = B2.y, b1 = B3.x, f1 = B3.y;
                u64 ab2[4] = { pk2(a0*b0,a0*b0), pk2(a0*b1,a0*b1),
                               pk2(a1*b0,a1*b0), pk2(a1*b1,a1*b1) };
                u64 ef2[4] = { pk2(e0*f0,e0*f0), pk2(e0*f1,e0*f1),
                               pk2(e1*f0,e1*f0), pk2(e1*f1,e1*f1) };
#pragma unroll
                for (int g = 0; g < 4; ++g) {
                    u64 t0 = mul2(w2[g*4+0], ef2[0]);
                    fma2(t0, w2[g*4+1], ef2[1]);
                    fma2(t0, w2[g*4+2], ef2[2]);
                    fma2(t0, w2[g*4+3], ef2[3]);
                    if (g == 0) accB = mul2(ab2[0], t0);
                    else        fma2(accB, ab2[g], t0);
                }
            }

            accA = add2(accA, __shfl_xor_sync(0xffffffffu, accA, 8));
            accB = add2(accB, __shfl_xor_sync(0xffffffffu, accB, 8));
            accA = add2(accA, __shfl_xor_sync(0xffffffffu, accA, 16));
            accB = add2(accB, __shfl_xor_sync(0xffffffffu, accB, 16));

            if (c == 0) {
                float r0, r1; up2(accA, r0, r1);
                float s0v, s1v; up2(accB, s0v, s1v);
                O[oo]                 = r0  + bz.x;
                O[oo + 16384]         = r1  + bz.y;
                O[oo + OSTR]          = s0v + bz.x;
                O[oo + OSTR + 16384]  = s1v + bz.y;
            }
            oo += 2 * OSTR;
        }
    }
}

extern "C" void kernel_launch(void* const* d_in, const int* in_sizes, int n_in,
                              void* d_out, int out_size)
{
    const float* X = (const float*)d_in[0];   // x        (64,4,2,256,256)
    const float* W = (const float*)d_in[1];   // tensors  (4,4,128,128,2,2,2,2,2)
    const float* B = (const float*)d_in[2];   // bias     (4,128,128,2)
    float* O = (float*)d_out;                 // out      (64,4,2,128,128)
    (void)in_sizes; (void)n_in; (void)out_size;
    ttn_kernel<<<128 * 16, 128>>>(X, W, B, O);
}

// round 17
// speedup vs baseline: 1.2702x; 1.2702x over previous
#include <cuda_runtime.h>

typedef unsigned long long u64;

// ---- packed f32x2 helpers (Blackwell sm_103a) ----
__device__ __forceinline__ u64 pk2(float a, float b) {
    u64 r; asm("mov.b64 %0,{%1,%2};" : "=l"(r) : "f"(a), "f"(b)); return r;
}
__device__ __forceinline__ void fma2(u64 &d, u64 a, u64 b) {
    asm("fma.rn.f32x2 %0,%1,%2,%0;" : "+l"(d) : "l"(a), "l"(b));
}
__device__ __forceinline__ u64 mul2(u64 a, u64 b) {
    u64 r; asm("mul.rn.f32x2 %0,%1,%2;" : "=l"(r) : "l"(a), "l"(b)); return r;
}
__device__ __forceinline__ u64 add2(u64 a, u64 b) {
    u64 r; asm("add.rn.f32x2 %0,%1,%2;" : "=l"(r) : "l"(a), "l"(b)); return r;
}
__device__ __forceinline__ void up2(u64 v, float &x, float &y) {
    asm("mov.b64 {%0,%1},%2;" : "=f"(x), "=f"(y) : "l"(v));
}
__device__ __forceinline__ void cp16(unsigned sa, const float4* ga) {
    asm volatile("cp.async.cg.shared.global [%0],[%1],16;" :: "r"(sa), "l"(ga));
}
__device__ __forceinline__ void cp_commit() {
    asm volatile("cp.async.commit_group;");
}
__device__ __forceinline__ void cp_wait1() {
    asm volatile("cp.async.wait_group 1;");
}

// Shapes: x:(64,4,2,256,256) w:(4,4,128,128,16,2) bias:(4,128,128,2) out:(64,4,2,128,128)
#define NPC 64                // all n per block (weights read from DRAM once)
#define XBUF 128              // float2 per x slice: 4(ir) * 4c * 8y = 1 KB
#define NBUF 16               // ring depth (slices), 16 KB
#define NSTR4 131072          // per-n stride in x, float4 units

// Block = 128 threads = 4 warps, 6 blocks/SM (6 independent barrier domains).
//   warp w owns output channel p = w; lane = c*8 + dy; y = y0 + dy (y-tile of 8).
// Grid = 128 (x) * 16 (y-tile) = 2048.
// x staged via cp.async.cg 16B (L1-bypass, half the instruction count):
// 64 float4 per slice; thread (h = tid>>6, fq = tid&63) covers float4 fq of
// slices s0+h and s0+h+2 in each 4-slice window. Weight prologue: 4 rounds
// through a 4 KB buffer (keeps smem at 20 KB -> L1D carveout stays large).
__global__ void __launch_bounds__(128, 6) ttn_kernel(
    const float* __restrict__ X, const float* __restrict__ W,
    const float* __restrict__ B, float* __restrict__ O)
{
    __shared__ __align__(16) float4 smw[256];            // 4 KB weight staging
    __shared__ __align__(16) float2 xsm[NBUF * XBUF];    // 16 KB x ring

    const int tid  = threadIdx.x;
    const int warp = tid >> 5;     // = p
    const int lane = tid & 31;
    const int c    = lane >> 3;
    const int dy   = lane & 7;

    const int bid = blockIdx.x;
    const int xp  = bid >> 4;
    const int y0  = (bid & 15) * 8;

    // ---- x staging roles: h = slice parity (0/1), fq = float4 within slice ----
    // fq -> pl (c_,i_,r_) and y-pair yy2: float2 idx = 2*fq = pl*32 + c_*8 + 2*yy2
    const int h  = tid >> 6;       // 0 or 1
    const int fq = tid & 63;
    const int pl_ = fq >> 4, c4_ = (fq >> 2) & 3, yy2_ = fq & 3;
    const int i4_ = (pl_ >> 1) & 1, r4_ = pl_ & 1;
    const int cc_ = (pl_ >> 2) | 0; // pl_ = c_*4? no: pl_ = fq>>4 in 0..3 is ir only
    // NOTE: slice layout is [ir(4)][c(4)][y(8)] float2 -> float4: [ir(4)][c(4)][y2(4)]
    const int ir4 = fq >> 4;                 // 0..3  (i,r)
    const int i4  = ir4 >> 1, r4 = ir4 & 1;
    const int c4  = (fq >> 2) & 3;
    const int y24 = fq & 3;
    const float4* X4 = (const float4*)X;
    // gmem float4 offset: ((c*2+i)*65536 + (2xp+r)*256 + y0 + 2*y2) floats / 4
    const int g4off = (c4 * 2 + i4) * 16384 + (2 * xp + r4) * 64 + (y0 >> 1) + y24;
    (void)pl_; (void)c4_; (void)yy2_; (void)i4_; (void)r4_; (void)cc_;

    unsigned sbase = (unsigned)__cvta_generic_to_shared(xsm);
    unsigned sa4   = sbase + (unsigned)fq * 16u;

    // prologue: slices 0..7 as two 4-slice groups (each thread: slices h,h+2 / h+4,h+6)
    {
        cp16(sa4 + (unsigned)(h)     * XBUF * 8u, X4 + (long)(h)     * NSTR4 + g4off);
        cp16(sa4 + (unsigned)(h + 2) * XBUF * 8u, X4 + (long)(h + 2) * NSTR4 + g4off);
        cp_commit();
        cp16(sa4 + (unsigned)(h + 4) * XBUF * 8u, X4 + (long)(h + 4) * NSTR4 + g4off);
        cp16(sa4 + (unsigned)(h + 6) * XBUF * 8u, X4 + (long)(h + 6) * NSTR4 + g4off);
        cp_commit();
    }

    // ---- stage weights gmem -> smem (coalesced, 4 rounds) -> registers ----
    u64 w2[16];
    for (int r = 0; r < 4; ++r) {
        __syncthreads();
#pragma unroll
        for (int k = 0; k < 2; ++k) {
            int G  = k * 128 + tid;        // 0..255
            int p  = G >> 6;
            int yy = (G >> 3) & 7;
            int j  = G & 7;
            float4 v = __ldg((const float4*)W +
                             (((r * 4 + p) * 16384 + xp * 128 + y0 + yy) * 8 + j));
            smw[p * 64 + yy * 8 + (j ^ yy ^ (p << 1))] = v;
        }
        __syncthreads();
        if (c == r) {
#pragma unroll
            for (int t = 0; t < 8; ++t) {
                float4 v = smw[warp * 64 + dy * 8 + (t ^ dy ^ (warp << 1))];
                w2[2 * t]     = pk2(v.x, v.y);
                w2[2 * t + 1] = pk2(v.z, v.w);
            }
        }
    }

    const float2 bz = *(const float2*)(B + ((warp * 128 + xp) * 128 + y0 + dy) * 2);
    const int OSTR = 4 * 2 * 16384;
    int oo = (warp * 2) * 16384 + xp * 128 + y0 + dy;   // advances per slice

    // moving refill pointer: window w refills slices 4w+8..4w+11
    const float4* gref = X4 + g4off + (long)(8 + h) * NSTR4;

#pragma unroll 4
    for (int w = 0; w < NPC / 4; ++w) {
        const int s0 = 4 * w;

        // refill BEFORE wait/sync (targets disjoint from windows w-1..w+1)
        if (w < NPC / 4 - 2) {
            cp16(sa4 + (unsigned)((s0 + 8 + h) & 15) * XBUF * 8u, gref);
            cp16(sa4 + (unsigned)((s0 + 10 + h) & 15) * XBUF * 8u, gref + 2L * NSTR4);
        }
        cp_commit();
        gref += 4L * NSTR4;

        cp_wait1();          // group holding this window's slices has landed
        __syncthreads();     // visible; retires window w-1's reads

        // two sub-pairs of slices; register-light
#pragma unroll
        for (int hh = 0; hh < 2; ++hh) {
            const float2* bufA = xsm + ((s0 + 2 * hh)     & 15) * XBUF;
            const float2* bufB = xsm + ((s0 + 2 * hh + 1) & 15) * XBUF;
            float2 A0 = bufA[lane],      A1 = bufA[32 + lane];
            float2 A2 = bufA[64 + lane], A3 = bufA[96 + lane];
            float2 B0 = bufB[lane],      B1 = bufB[32 + lane];
            float2 B2 = bufB[64 + lane], B3 = bufB[96 + lane];

            u64 accA, accB;
            {
                const float a0 = A0.x, e0 = A0.y, b0 = A1.x, f0 = A1.y;
                const float a1 = A2.x, e1 = A2.y, b1 = A3.x, f1 = A3.y;
                u64 ab2[4] = { pk2(a0*b0,a0*b0), pk2(a0*b1,a0*b1),
                               pk2(a1*b0,a1*b0), pk2(a1*b1,a1*b1) };
                u64 ef2[4] = { pk2(e0*f0,e0*f0), pk2(e0*f1,e0*f1),
                               pk2(e1*f0,e1*f0), pk2(e1*f1,e1*f1) };
#pragma unroll
                for (int g = 0; g < 4; ++g) {
                    u64 t0 = mul2(w2[g*4+0], ef2[0]);
                    fma2(t0, w2[g*4+1], ef2[1]);
                    fma2(t0, w2[g*4+2], ef2[2]);
                    fma2(t0, w2[g*4+3], ef2[3]);
                    if (g == 0) accA = mul2(ab2[0], t0);
                    else        fma2(accA, ab2[g], t0);
                }
            }
            {
                const float a0 = B0.x, e0 = B0.y, b0 = B1.x, f0 = B1.y;
                const float a1 = B2.x, e1 = B2.y, b1 = B3.x, f1 = B3.y;
                u64 ab2[4] = { pk2(a0*b0,a0*b0), pk2(a0*b1,a0*b1),
                               pk2(a1*b0,a1*b0), pk2(a1*b1,a1*b1) };
                u64 ef2[4] = { pk2(e0*f0,e0*f0), pk2(e0*f1,e0*f1),
                               pk2(e1*f0,e1*f0), pk2(e1*f1,e1*f1) };
#pragma unroll
                for (int g = 0; g < 4; ++g) {
                    u64 t0 = mul2(w2[g*4+0], ef2[0]);
                    fma2(t0, w2[g*4+1], ef2[1]);
                    fma2(t0, w2[g*4+2], ef2[2]);
                    fma2(t0, w2[g*4+3], ef2[3]);
                    if (g == 0) accB = mul2(ab2[0], t0);
                    else        fma2(accB, ab2[g], t0);
                }
            }

            accA = add2(accA, __shfl_xor_sync(0xffffffffu, accA, 8));
            accB = add2(accB, __shfl_xor_sync(0xffffffffu, accB, 8));
            accA = add2(accA, __shfl_xor_sync(0xffffffffu, accA, 16));
            accB = add2(accB, __shfl_xor_sync(0xffffffffu, accB, 16));

            if (c == 0) {
                float r0, r1; up2(accA, r0, r1);
                float s0v, s1v; up2(accB, s0v, s1v);
                O[oo]                 = r0  + bz.x;
                O[oo + 16384]         = r1  + bz.y;
                O[oo + OSTR]          = s0v + bz.x;
                O[oo + OSTR + 16384]  = s1v + bz.y;
            }
            oo += 2 * OSTR;
        }
    }
}

extern "C" void kernel_launch(void* const* d_in, const int* in_sizes, int n_in,
                              void* d_out, int out_size)
{
    const float* X = (const float*)d_in[0];   // x        (64,4,2,256,256)
    const float* W = (const float*)d_in[1];   // tensors  (4,4,128,128,2,2,2,2,2)
    const float* B = (const float*)d_in[2];   // bias     (4,128,128,2)
    float* O = (float*)d_out;                 // out      (64,4,2,128,128)
    (void)in_sizes; (void)n_in; (void)out_size;
    ttn_kernel<<<128 * 16, 128>>>(X, W, B, O);
}